// round 9
// baseline (speedup 1.0000x reference)
#include <cuda_runtime.h>
#include <cuda_fp16.h>
#include <cstdint>

#define NB    8
#define NPTS  8192
#define E     128
#define HG    64
#define WG    64
#define SG    (HG*WG)          // 4096
#define NCELL (NB*SG)          // 32768
#define NPT   (NB*NPTS)        // 65536
#define NROWS (NPT+NCELL)      // 98304
#define MAXP  20
#define NH    8

#define SK 136                 // padded k-stride (fp16 elements)

// ---------------- scratch ----------------
__device__ int   g_count[NCELL];
__device__ int   g_slots[NCELL*MAXP];
__device__ float g_q[E];
__device__ float g_score[(size_t)NROWS*NH];    // point scores then grid scores
__device__ float g_V[(size_t)NROWS*E];         // z@Wv then z_grid@Wv
__device__ float g_attout[(size_t)NCELL*E];
// pre-split weights (fp16, transposed [n][k]): Wv blob = [W 128xSK][AT 8xSK]
__device__ __align__(16) __half g_WvSp[136*SK];
__device__ __align__(16) __half g_WoSp[128*SK];

// ---------------- mma / ldmatrix helpers ----------------
__device__ __forceinline__ void mma16816(float* c, const uint32_t* a, uint32_t b0, uint32_t b1) {
    asm volatile(
        "mma.sync.aligned.m16n8k16.row.col.f32.f16.f16.f32 "
        "{%0,%1,%2,%3}, {%4,%5,%6,%7}, {%8,%9}, {%0,%1,%2,%3};"
        : "+f"(c[0]), "+f"(c[1]), "+f"(c[2]), "+f"(c[3])
        : "r"(a[0]), "r"(a[1]), "r"(a[2]), "r"(a[3]), "r"(b0), "r"(b1));
}
__device__ __forceinline__ void ldsm_x4(uint32_t* r, uint32_t a) {
    asm volatile("ldmatrix.sync.aligned.m8n8.x4.shared.b16 {%0,%1,%2,%3}, [%4];"
        : "=r"(r[0]), "=r"(r[1]), "=r"(r[2]), "=r"(r[3]) : "r"(a));
}
__device__ __forceinline__ void ldsm_x2(uint32_t* r, uint32_t a) {
    asm volatile("ldmatrix.sync.aligned.m8n8.x2.shared.b16 {%0,%1}, [%2];"
        : "=r"(r[0]), "=r"(r[1]) : "r"(a));
}
__device__ __forceinline__ void cp_async16(uint32_t dst, const void* src) {
    asm volatile("cp.async.cg.shared.global [%0], [%1], 16;" :: "r"(dst), "l"(src));
}

// ---------------- fused GEMM (+ optional score), fp16 single pass ----------------
// 64x128 tile, 256 thr = 8 warps (2m x 4n); each warp 32x32 = 2x4 m16n8 tiles.
#define SM_A  0
#define SM_B  (64*SK)
#define SM_SB (192*SK)
#define GEMM_SMEM (200*SK*2)     // 54400 B -> 3 CTAs/SM

template<bool DO_SCORE>
__global__ void __launch_bounds__(256, 3) gemm_tc(const float* __restrict__ Z1,
                                                  const float* __restrict__ Z2, int nb1,
                                                  const __half* __restrict__ Wsp,
                                                  int wbytes,
                                                  float* __restrict__ C,
                                                  float* __restrict__ Sout) {
    extern __shared__ __half sm[];
    const int t    = threadIdx.x;
    const int wid  = t >> 5;
    const int lane = t & 31;
    const int gRow0 = blockIdx.x * 64;
    const float* src;
    int m0;
    if ((int)blockIdx.x < nb1) { src = Z1; m0 = gRow0; }
    else                       { src = Z2; m0 = (blockIdx.x - nb1) * 64; }

    const uint32_t sb = (uint32_t)__cvta_generic_to_shared(sm);

    // ---- B (+score) staging: linear cp.async copy of pre-converted blob ----
    {
        const char* gsrc = (const char*)Wsp;
        uint32_t bdst = sb + SM_B*2;
        for (int off = t*16; off < wbytes; off += 256*16)
            cp_async16(bdst + off, gsrc + off);
        asm volatile("cp.async.commit_group;");
    }

    // ---- A staging: each thread one quarter-row (32 floats) -> fp16 ----
    {
        int row = t >> 2;
        int kq  = (t & 3) << 5;
        const float4* zr = (const float4*)(src + (size_t)(m0 + row) * E + kq);
        __half* a = sm + SM_A + row*SK + kq;
        #pragma unroll
        for (int i = 0; i < 8; i++) {
            float4 v = zr[i];
            ((__half2*)(a + i*4))[0] = __floats2half2_rn(v.x, v.y);
            ((__half2*)(a + i*4))[1] = __floats2half2_rn(v.z, v.w);
        }
    }
    asm volatile("cp.async.wait_group 0;" ::: "memory");
    __syncthreads();

    const int mw = wid >> 2;            // 0..1 : rows mw*32
    const int nw = wid & 3;             // 0..3 : cols nw*32
    const int g  = lane >> 2;
    const int tg = lane & 3;

    // per-lane ldmatrix addresses (byte offsets)
    uint32_t aA[2];
    #pragma unroll
    for (int mt = 0; mt < 2; mt++) {
        int row = mw*32 + mt*16 + (lane & 15);
        int col = (lane >> 4) << 3;
        aA[mt] = sb + (SM_A + row*SK + col) * 2;
    }
    uint32_t aB[2];
    #pragma unroll
    for (int c = 0; c < 2; c++) {
        int row = nw*32 + c*16 + (lane & 7) + ((lane >> 4) << 3);
        int col = ((lane >> 3) & 1) << 3;
        aB[c] = sb + (SM_B + row*SK + col) * 2;
    }
    uint32_t aS = 0;
    if (DO_SCORE) {
        int row = lane & 7;
        int col = ((lane >> 3) & 1) << 3;
        aS = sb + (SM_SB + row*SK + col) * 2;
    }

    float acc[2][4][4];
    #pragma unroll
    for (int a = 0; a < 2; a++)
        #pragma unroll
        for (int b = 0; b < 4; b++)
            #pragma unroll
            for (int c = 0; c < 4; c++) acc[a][b][c] = 0.f;
    float sacc[2][4] = {{0.f,0.f,0.f,0.f},{0.f,0.f,0.f,0.f}};

    #pragma unroll
    for (int ks = 0; ks < 8; ks++) {
        const uint32_t ko = ks * 32;    // 16 fp16 = 32 bytes
        uint32_t ah[2][4];
        ldsm_x4(ah[0], aA[0] + ko);
        ldsm_x4(ah[1], aA[1] + ko);

        if (DO_SCORE && nw == 0) {
            uint32_t sh[2];
            ldsm_x2(sh, aS + ko);
            mma16816(sacc[0], ah[0], sh[0], sh[1]);
            mma16816(sacc[1], ah[1], sh[0], sh[1]);
        }
        #pragma unroll
        for (int c = 0; c < 2; c++) {
            uint32_t bh[4];
            ldsm_x4(bh, aB[c] + ko);
            #pragma unroll
            for (int mt = 0; mt < 2; mt++) {
                mma16816(acc[mt][2*c+0], ah[mt], bh[0], bh[1]);
                mma16816(acc[mt][2*c+1], ah[mt], bh[2], bh[3]);
            }
        }
    }

    // ---- epilogue ----
    #pragma unroll
    for (int mt = 0; mt < 2; mt++) {
        int row = gRow0 + mw*32 + mt*16 + g;
        #pragma unroll
        for (int nt = 0; nt < 4; nt++) {
            int col = nw*32 + nt*8 + tg*2;
            *(float2*)(C + (size_t)row * E + col) =
                make_float2(acc[mt][nt][0], acc[mt][nt][1]);
            *(float2*)(C + (size_t)(row + 8) * E + col) =
                make_float2(acc[mt][nt][2], acc[mt][nt][3]);
        }
    }
    if (DO_SCORE && nw == 0) {
        #pragma unroll
        for (int mt = 0; mt < 2; mt++) {
            int row = gRow0 + mw*32 + mt*16 + g;
            *(float2*)(Sout + (size_t)row * NH + tg*2) =
                make_float2(sacc[mt][0], sacc[mt][1]);
            *(float2*)(Sout + (size_t)(row + 8) * NH + tg*2) =
                make_float2(sacc[mt][2], sacc[mt][3]);
        }
    }
}

// ---------------- fused setup kernels ----------------
// setup1: blocks 0..127 -> transpose+convert Wv & Wo; block 128 -> q = latent@Wq;
//         blocks 129..256 -> zero g_count
__global__ void setup1(const float* __restrict__ Wv, const float* __restrict__ Wo,
                       const float* __restrict__ latent, const float* __restrict__ Wq) {
    __shared__ float lat[E];
    __shared__ float part[2][E];
    int b = blockIdx.x;
    int t = threadIdx.x;
    if (b < 128) {
        int n = b;
        if (t < 128) g_WvSp[n*SK + t] = __float2half(Wv[(size_t)t*E + n]);
        else {
            int k = t - 128;
            g_WoSp[n*SK + k] = __float2half(Wo[(size_t)k*E + n]);
        }
    } else if (b == 128) {
        int tt = t & 127;
        int dd = t >> 7;       // 0..1
        if (t < E) lat[t] = latent[t];
        __syncthreads();
        float a = 0.f;
        #pragma unroll
        for (int i = 0; i < 64; i++) {
            int d = dd*64 + i;
            a += lat[d] * Wq[(size_t)d*E + tt];
        }
        part[dd][tt] = a;
        __syncthreads();
        if (t < E) g_q[t] = part[0][t] + part[1][t];
    } else {
        g_count[(b - 129)*256 + t] = 0;
    }
}

// setup2: blocks 0..3 -> AT[h][k] = 0.25*sum_i Wk[k][16h+i]*q[16h+i] (fp16, into blob tail);
//         blocks 4..259 -> scatter points into cells
__global__ void setup2(const float* __restrict__ Wk, const float* __restrict__ x) {
    __shared__ float qs[E];
    int b = blockIdx.x;
    int t = threadIdx.x;
    if (b < 4) {
        if (t < E) qs[t] = g_q[t];
        __syncthreads();
        int id = b*256 + t;          // 0..1023
        int k = id >> 3, h = id & 7;
        float s = 0.f;
        #pragma unroll
        for (int i = 0; i < 16; i++) s += Wk[(size_t)k*E + h*16 + i] * qs[h*16 + i];
        g_WvSp[128*SK + h*SK + k] = __float2half(s * 0.25f);
    } else {
        int p = (b - 4)*256 + t;
        int bb = p >> 13;
        float x0 = x[2*p], x1 = x[2*p+1];
        int i0 = (int)rintf(x0 * 63.0f); i0 = min(max(i0, 0), 63);
        int i1 = (int)rintf(x1 * 63.0f); i1 = min(max(i1, 0), 63);
        int cell = bb*SG + i0*WG + i1;
        int slot = atomicAdd(&g_count[cell], 1);
        if (slot < MAXP) g_slots[cell*MAXP + slot] = p;
    }
}

__global__ void attn_kernel() {
    const float* V   = g_V;
    const float* gV  = g_V + (size_t)NPT*E;
    const float* Ssc = g_score;
    const float* gS  = g_score + (size_t)NPT*NH;
    float* out = g_attout;

    __shared__ int toks[8][MAXP];
    int warp = threadIdx.x >> 5, lane = threadIdx.x & 31;
    int g = blockIdx.x*8 + warp;
    int cnt = g_count[g];
    int kk = min(cnt, MAXP);
    if (lane < kk) toks[warp][lane] = g_slots[g*MAXP + lane];
    __syncwarp();

    int h = lane >> 2;
    float m = gS[g*NH + h];
    for (int tkn = 0; tkn < kk; tkn++) {
        int p = toks[warp][tkn];
        m = fmaxf(m, Ssc[p*NH + h]);
    }
    float e = expf(gS[g*NH + h] - m);
    float sum = e;
    float4 gv = *(const float4*)(gV + (size_t)g*E + lane*4);
    float4 acc = make_float4(e*gv.x, e*gv.y, e*gv.z, e*gv.w);
    for (int tkn = 0; tkn < kk; tkn++) {
        int p = toks[warp][tkn];
        float w = expf(Ssc[p*NH + h] - m);
        sum += w;
        float4 v = *(const float4*)(V + (size_t)p*E + lane*4);
        acc.x += w*v.x; acc.y += w*v.y; acc.z += w*v.z; acc.w += w*v.w;
    }
    float inv = 1.0f / sum;
    float4 o = make_float4(acc.x*inv, acc.y*inv, acc.z*inv, acc.w*inv);
    *(float4*)(out + (size_t)g*E + lane*4) = o;
}

// ---------------- launch ----------------
extern "C" void kernel_launch(void* const* d_in, const int* in_sizes, int n_in,
                              void* d_out, int out_size) {
    const float* x      = (const float*)d_in[0];
    const float* z      = (const float*)d_in[1];
    const float* x_grid = (const float*)d_in[2];
    const float* z_grid = (const float*)d_in[3];
    const float* latent = (const float*)d_in[4];
    const float* Wq     = (const float*)d_in[5];
    const float* Wk     = (const float*)d_in[6];
    const float* Wv     = (const float*)d_in[7];
    const float* Wo     = (const float*)d_in[8];

    float* out = (float*)d_out;
    float* zg_out = out;
    const int XG_ELEMS = NB*SG*2;
    if (out_size == NCELL*E + XG_ELEMS) {
        cudaMemcpyAsync(out, x_grid, (size_t)XG_ELEMS*sizeof(float),
                        cudaMemcpyDeviceToDevice);
        zg_out = out + XG_ELEMS;
    }

    void *pV, *pS, *pAO, *pWv, *pWo;
    cudaGetSymbolAddress(&pV,  g_V);
    cudaGetSymbolAddress(&pS,  g_score);
    cudaGetSymbolAddress(&pAO, g_attout);
    cudaGetSymbolAddress(&pWv, g_WvSp);
    cudaGetSymbolAddress(&pWo, g_WoSp);

    cudaFuncSetAttribute(gemm_tc<true>,  cudaFuncAttributeMaxDynamicSharedMemorySize, GEMM_SMEM);
    cudaFuncSetAttribute(gemm_tc<false>, cudaFuncAttributeMaxDynamicSharedMemorySize, GEMM_SMEM);

    setup1<<<257, 256>>>(Wv, Wo, latent, Wq);
    setup2<<<260, 256>>>(Wk, x);

    gemm_tc<true><<<NROWS/64, 256, GEMM_SMEM>>>(z, z_grid, NPT/64,
                                                (const __half*)pWv, 136*SK*2,
                                                (float*)pV, (float*)pS);
    attn_kernel<<<NCELL/8, 256>>>();

    gemm_tc<false><<<NCELL/64, 256, GEMM_SMEM>>>((const float*)pAO, (const float*)pAO,
                                                 NCELL/64,
                                                 (const __half*)pWo, 128*SK*2,
                                                 zg_out, nullptr);
}

// round 11
// speedup vs baseline: 1.0283x; 1.0283x over previous
#include <cuda_runtime.h>
#include <cuda_bf16.h>
#include <cstdint>

#define NB    8
#define NPTS  8192
#define E     128
#define HG    64
#define WG    64
#define SG    (HG*WG)          // 4096
#define NCELL (NB*SG)          // 32768
#define NPT   (NB*NPTS)        // 65536
#define NROWS (NPT+NCELL)      // 98304
#define MAXP  20
#define NH    8

#define SK 136                 // padded k-stride (bf16 elements)

// ---------------- scratch ----------------
__device__ int   g_count[NCELL];
__device__ int   g_slots[NCELL*MAXP];
__device__ float g_q[E];
__device__ float g_score[(size_t)NROWS*NH];    // point scores then grid scores
__device__ float g_V[(size_t)NROWS*E];         // z@Wv then z_grid@Wv
// pre-split weights (bf16 hi/lo, transposed [n][k]):
// Wv blob = [Whi 128xSK][Wlo 128xSK][ATh 8xSK][ATl 8xSK]
__device__ __align__(16) __nv_bfloat16 g_WvSp[272*SK];
__device__ __align__(16) __nv_bfloat16 g_WoSp[256*SK];

// ---------------- mma / ldmatrix helpers ----------------
__device__ __forceinline__ void mma16816(float* c, const uint32_t* a, uint32_t b0, uint32_t b1) {
    asm volatile(
        "mma.sync.aligned.m16n8k16.row.col.f32.bf16.bf16.f32 "
        "{%0,%1,%2,%3}, {%4,%5,%6,%7}, {%8,%9}, {%0,%1,%2,%3};"
        : "+f"(c[0]), "+f"(c[1]), "+f"(c[2]), "+f"(c[3])
        : "r"(a[0]), "r"(a[1]), "r"(a[2]), "r"(a[3]), "r"(b0), "r"(b1));
}
__device__ __forceinline__ void ldsm_x4(uint32_t* r, uint32_t a) {
    asm volatile("ldmatrix.sync.aligned.m8n8.x4.shared.b16 {%0,%1,%2,%3}, [%4];"
        : "=r"(r[0]), "=r"(r[1]), "=r"(r[2]), "=r"(r[3]) : "r"(a));
}
__device__ __forceinline__ void ldsm_x2(uint32_t* r, uint32_t a) {
    asm volatile("ldmatrix.sync.aligned.m8n8.x2.shared.b16 {%0,%1}, [%2];"
        : "=r"(r[0]), "=r"(r[1]) : "r"(a));
}
__device__ __forceinline__ uint32_t pack_hi(float x, float y) {
    __nv_bfloat162 h = __halves2bfloat162(__float2bfloat16(x), __float2bfloat16(y));
    return *(uint32_t*)&h;
}
__device__ __forceinline__ uint32_t pack_lo(float x, float y) {
    __nv_bfloat16 hx = __float2bfloat16(x), hy = __float2bfloat16(y);
    __nv_bfloat162 l = __halves2bfloat162(__float2bfloat16(x - __bfloat162float(hx)),
                                          __float2bfloat16(y - __bfloat162float(hy)));
    return *(uint32_t*)&l;
}
__device__ __forceinline__ void cp_async16(uint32_t dst, const void* src) {
    asm volatile("cp.async.cg.shared.global [%0], [%1], 16;" :: "r"(dst), "l"(src));
}

// shared mainloop: A[64][128] hi/lo in smem, B[128][128] hi/lo in smem, 3-pass bf16
#define SM_AHI 0
#define SM_ALO (64*SK)
#define SM_BHI (128*SK)
#define SM_BLO (256*SK)
#define SM_SBH (384*SK)
#define SM_SBL (392*SK)
#define GEMM1_SMEM (400*SK*2)    // 108800 B  (with score cols)
#define GEMM2_SMEM (384*SK*2)    // 104448 B  (no score)

template<bool DO_SCORE>
__device__ __forceinline__ void gemm_mainloop(uint32_t sb, int wid, int lane,
                                              int gRow0, float* __restrict__ C,
                                              float* __restrict__ Sout) {
    const int mw = wid >> 2;            // 0..1 : rows mw*32
    const int nw = wid & 3;             // 0..3 : cols nw*32
    const int g  = lane >> 2;
    const int tg = lane & 3;

    uint32_t aAh[2], aAl[2];
    #pragma unroll
    for (int mt = 0; mt < 2; mt++) {
        int row = mw*32 + mt*16 + (lane & 15);
        int col = (lane >> 4) << 3;
        aAh[mt] = sb + (SM_AHI + row*SK + col) * 2;
        aAl[mt] = sb + (SM_ALO + row*SK + col) * 2;
    }
    uint32_t aBh[2], aBl[2];
    #pragma unroll
    for (int c = 0; c < 2; c++) {
        int row = nw*32 + c*16 + (lane & 7) + ((lane >> 4) << 3);
        int col = ((lane >> 3) & 1) << 3;
        aBh[c] = sb + (SM_BHI + row*SK + col) * 2;
        aBl[c] = sb + (SM_BLO + row*SK + col) * 2;
    }
    uint32_t aSh = 0, aSl = 0;
    if (DO_SCORE) {
        int row = lane & 7;
        int col = ((lane >> 3) & 1) << 3;
        aSh = sb + (SM_SBH + row*SK + col) * 2;
        aSl = sb + (SM_SBL + row*SK + col) * 2;
    }

    float acc[2][4][4];
    #pragma unroll
    for (int a = 0; a < 2; a++)
        #pragma unroll
        for (int b = 0; b < 4; b++)
            #pragma unroll
            for (int c = 0; c < 4; c++) acc[a][b][c] = 0.f;
    float sacc[2][4] = {{0.f,0.f,0.f,0.f},{0.f,0.f,0.f,0.f}};

    #pragma unroll
    for (int ks = 0; ks < 8; ks++) {
        const uint32_t ko = ks * 32;
        uint32_t ah[2][4], al[2][4];
        ldsm_x4(ah[0], aAh[0] + ko);
        ldsm_x4(ah[1], aAh[1] + ko);
        ldsm_x4(al[0], aAl[0] + ko);
        ldsm_x4(al[1], aAl[1] + ko);

        if (DO_SCORE && nw == 0) {
            uint32_t sh[2], sl[2];
            ldsm_x2(sh, aSh + ko);
            ldsm_x2(sl, aSl + ko);
            #pragma unroll
            for (int mt = 0; mt < 2; mt++) {
                mma16816(sacc[mt], ah[mt], sh[0], sh[1]);
                mma16816(sacc[mt], al[mt], sh[0], sh[1]);
                mma16816(sacc[mt], ah[mt], sl[0], sl[1]);
            }
        }
        #pragma unroll
        for (int c = 0; c < 2; c++) {
            uint32_t bh[4], bl[4];
            ldsm_x4(bh, aBh[c] + ko);
            ldsm_x4(bl, aBl[c] + ko);
            #pragma unroll
            for (int mt = 0; mt < 2; mt++) {
                mma16816(acc[mt][2*c+0], ah[mt], bh[0], bh[1]);
                mma16816(acc[mt][2*c+1], ah[mt], bh[2], bh[3]);
                mma16816(acc[mt][2*c+0], al[mt], bh[0], bh[1]);
                mma16816(acc[mt][2*c+1], al[mt], bh[2], bh[3]);
                mma16816(acc[mt][2*c+0], ah[mt], bl[0], bl[1]);
                mma16816(acc[mt][2*c+1], ah[mt], bl[2], bl[3]);
            }
        }
    }

    #pragma unroll
    for (int mt = 0; mt < 2; mt++) {
        int row = gRow0 + mw*32 + mt*16 + g;
        #pragma unroll
        for (int nt = 0; nt < 4; nt++) {
            int col = nw*32 + nt*8 + tg*2;
            *(float2*)(C + (size_t)row * E + col) =
                make_float2(acc[mt][nt][0], acc[mt][nt][1]);
            *(float2*)(C + (size_t)(row + 8) * E + col) =
                make_float2(acc[mt][nt][2], acc[mt][nt][3]);
        }
    }
    if (DO_SCORE && nw == 0) {
        #pragma unroll
        for (int mt = 0; mt < 2; mt++) {
            int row = gRow0 + mw*32 + mt*16 + g;
            *(float2*)(Sout + (size_t)row * NH + tg*2) =
                make_float2(sacc[mt][0], sacc[mt][1]);
            *(float2*)(Sout + (size_t)(row + 8) * NH + tg*2) =
                make_float2(sacc[mt][2], sacc[mt][3]);
        }
    }
}

// ---------------- GEMM 1: V = [z; z_grid] @ Wv  (+ scores) ----------------
__global__ void __launch_bounds__(256, 2) gemm_v(const float* __restrict__ Z1,
                                                 const float* __restrict__ Z2, int nb1,
                                                 float* __restrict__ C,
                                                 float* __restrict__ Sout) {
    extern __shared__ __nv_bfloat16 sm[];
    const int t    = threadIdx.x;
    const int wid  = t >> 5;
    const int lane = t & 31;
    const int gRow0 = blockIdx.x * 64;
    const float* src;
    int m0;
    if ((int)blockIdx.x < nb1) { src = Z1; m0 = gRow0; }
    else                       { src = Z2; m0 = (blockIdx.x - nb1) * 64; }

    const uint32_t sb = (uint32_t)__cvta_generic_to_shared(sm);

    // B (+score) staging: linear cp.async of pre-split blob
    {
        const char* gsrc = (const char*)g_WvSp;
        uint32_t bdst = sb + SM_BHI*2;
        const int wbytes = 272*SK*2;
        for (int off = t*16; off < wbytes; off += 256*16)
            cp_async16(bdst + off, gsrc + off);
        asm volatile("cp.async.commit_group;");
    }
    // A staging: each thread one quarter-row (32 floats), split hi/lo
    {
        int row = t >> 2;
        int kq  = (t & 3) << 5;
        const float4* zr = (const float4*)(src + (size_t)(m0 + row) * E + kq);
        __nv_bfloat16* ah = sm + SM_AHI + row*SK + kq;
        __nv_bfloat16* al = sm + SM_ALO + row*SK + kq;
        #pragma unroll
        for (int i = 0; i < 8; i++) {
            float4 v = zr[i];
            ((uint32_t*)(ah + i*4))[0] = pack_hi(v.x, v.y);
            ((uint32_t*)(ah + i*4))[1] = pack_hi(v.z, v.w);
            ((uint32_t*)(al + i*4))[0] = pack_lo(v.x, v.y);
            ((uint32_t*)(al + i*4))[1] = pack_lo(v.z, v.w);
        }
    }
    asm volatile("cp.async.wait_group 0;" ::: "memory");
    __syncthreads();

    gemm_mainloop<true>(sb, wid, lane, gRow0, C, Sout);
}

// ---------------- GEMM 2: out = attn(...) @ Wo, attention fused in prologue ----------------
__global__ void __launch_bounds__(256, 2) gemm_att(float* __restrict__ C) {
    extern __shared__ __nv_bfloat16 sm[];
    __shared__ int toks[8][MAXP];
    const int t    = threadIdx.x;
    const int wid  = t >> 5;
    const int lane = t & 31;
    const int c0   = blockIdx.x * 64;          // cell base == output row base

    const uint32_t sb = (uint32_t)__cvta_generic_to_shared(sm);

    // B staging
    {
        const char* gsrc = (const char*)g_WoSp;
        uint32_t bdst = sb + SM_BHI*2;
        const int wbytes = 256*SK*2;
        for (int off = t*16; off < wbytes; off += 256*16)
            cp_async16(bdst + off, gsrc + off);
        asm volatile("cp.async.commit_group;");
    }

    // attention prologue: each warp computes 8 cells -> smem A rows (bf16 hi/lo)
    {
        const float* V   = g_V;
        const float* gV  = g_V + (size_t)NPT*E;
        const float* Ssc = g_score;
        const float* gS  = g_score + (size_t)NPT*NH;
        const int h = lane >> 2;

        for (int j = 0; j < 8; j++) {
            int c = c0 + wid*8 + j;
            int kk = min(g_count[c], MAXP);
            if (lane < kk) toks[wid][lane] = g_slots[c*MAXP + lane];
            __syncwarp();

            float e = __expf(gS[(size_t)c*NH + h]);
            float sum = e;
            float4 gv = *(const float4*)(gV + (size_t)c*E + lane*4);
            float4 acc = make_float4(e*gv.x, e*gv.y, e*gv.z, e*gv.w);
            for (int tkn = 0; tkn < kk; tkn++) {
                int p = toks[wid][tkn];
                float w = __expf(Ssc[(size_t)p*NH + h]);
                sum += w;
                float4 v = *(const float4*)(V + (size_t)p*E + lane*4);
                acc.x += w*v.x; acc.y += w*v.y; acc.z += w*v.z; acc.w += w*v.w;
            }
            float inv = 1.0f / sum;
            acc.x *= inv; acc.y *= inv; acc.z *= inv; acc.w *= inv;

            int row = wid*8 + j;
            __nv_bfloat16* ah = sm + SM_AHI + row*SK + lane*4;
            __nv_bfloat16* al = sm + SM_ALO + row*SK + lane*4;
            ((uint32_t*)ah)[0] = pack_hi(acc.x, acc.y);
            ((uint32_t*)ah)[1] = pack_hi(acc.z, acc.w);
            ((uint32_t*)al)[0] = pack_lo(acc.x, acc.y);
            ((uint32_t*)al)[1] = pack_lo(acc.z, acc.w);
            __syncwarp();
        }
    }
    asm volatile("cp.async.wait_group 0;" ::: "memory");
    __syncthreads();

    gemm_mainloop<false>(sb, wid, lane, c0, C, nullptr);
}

// ---------------- fused setup kernels ----------------
// setup1: blocks 0..127 -> split+transpose Wv & Wo; block 128 -> q = latent@Wq;
//         blocks 129..256 -> zero g_count
__global__ void setup1(const float* __restrict__ Wv, const float* __restrict__ Wo,
                       const float* __restrict__ latent, const float* __restrict__ Wq) {
    __shared__ float lat[E];
    __shared__ float part[2][E];
    int b = blockIdx.x;
    int t = threadIdx.x;
    if (b < 128) {
        int n = b;
        if (t < 128) {
            int k = t;
            float v = Wv[(size_t)k*E + n];
            __nv_bfloat16 h = __float2bfloat16(v);
            g_WvSp[n*SK + k] = h;
            g_WvSp[128*SK + n*SK + k] = __float2bfloat16(v - __bfloat162float(h));
        } else {
            int k = t - 128;
            float v = Wo[(size_t)k*E + n];
            __nv_bfloat16 h = __float2bfloat16(v);
            g_WoSp[n*SK + k] = h;
            g_WoSp[128*SK + n*SK + k] = __float2bfloat16(v - __bfloat162float(h));
        }
    } else if (b == 128) {
        int tt = t & 127;
        int dd = t >> 7;       // 0..1
        if (t < E) lat[t] = latent[t];
        __syncthreads();
        float a = 0.f;
        #pragma unroll
        for (int i = 0; i < 64; i++) {
            int d = dd*64 + i;
            a += lat[d] * Wq[(size_t)d*E + tt];
        }
        part[dd][tt] = a;
        __syncthreads();
        if (t < E) g_q[t] = part[0][t] + part[1][t];
    } else {
        g_count[(b - 129)*256 + t] = 0;
    }
}

// setup2: blocks 0..3 -> AT[h][k] hi/lo into Wv blob tail; blocks 4..259 -> scatter
__global__ void setup2(const float* __restrict__ Wk, const float* __restrict__ x) {
    __shared__ float qs[E];
    int b = blockIdx.x;
    int t = threadIdx.x;
    if (b < 4) {
        if (t < E) qs[t] = g_q[t];
        __syncthreads();
        int id = b*256 + t;          // 0..1023
        int k = id >> 3, h = id & 7;
        float s = 0.f;
        #pragma unroll
        for (int i = 0; i < 16; i++) s += Wk[(size_t)k*E + h*16 + i] * qs[h*16 + i];
        s *= 0.25f;
        __nv_bfloat16 hi = __float2bfloat16(s);
        g_WvSp[256*SK + h*SK + k] = hi;
        g_WvSp[264*SK + h*SK + k] = __float2bfloat16(s - __bfloat162float(hi));
    } else {
        int p = (b - 4)*256 + t;
        int bb = p >> 13;
        float x0 = x[2*p], x1 = x[2*p+1];
        int i0 = (int)rintf(x0 * 63.0f); i0 = min(max(i0, 0), 63);
        int i1 = (int)rintf(x1 * 63.0f); i1 = min(max(i1, 0), 63);
        int cell = bb*SG + i0*WG + i1;
        int slot = atomicAdd(&g_count[cell], 1);
        if (slot < MAXP) g_slots[cell*MAXP + slot] = p;
    }
}

// ---------------- launch ----------------
extern "C" void kernel_launch(void* const* d_in, const int* in_sizes, int n_in,
                              void* d_out, int out_size) {
    const float* x      = (const float*)d_in[0];
    const float* z      = (const float*)d_in[1];
    const float* x_grid = (const float*)d_in[2];
    const float* z_grid = (const float*)d_in[3];
    const float* latent = (const float*)d_in[4];
    const float* Wq     = (const float*)d_in[5];
    const float* Wk     = (const float*)d_in[6];
    const float* Wv     = (const float*)d_in[7];
    const float* Wo     = (const float*)d_in[8];

    float* out = (float*)d_out;
    float* zg_out = out;
    const int XG_ELEMS = NB*SG*2;
    if (out_size == NCELL*E + XG_ELEMS) {
        cudaMemcpyAsync(out, x_grid, (size_t)XG_ELEMS*sizeof(float),
                        cudaMemcpyDeviceToDevice);
        zg_out = out + XG_ELEMS;
    }

    void *pV, *pS;
    cudaGetSymbolAddress(&pV, g_V);
    cudaGetSymbolAddress(&pS, g_score);

    cudaFuncSetAttribute(gemm_v,   cudaFuncAttributeMaxDynamicSharedMemorySize, GEMM1_SMEM);
    cudaFuncSetAttribute(gemm_att, cudaFuncAttributeMaxDynamicSharedMemorySize, GEMM2_SMEM);

    setup1<<<257, 256>>>(Wv, Wo, latent, Wq);
    setup2<<<260, 256>>>(Wk, x);

    gemm_v<<<NROWS/64, 256, GEMM1_SMEM>>>(z, z_grid, NPT/64, (float*)pV, (float*)pS);
    gemm_att<<<NCELL/64, 256, GEMM2_SMEM>>>(zg_out);
}

// round 15
// speedup vs baseline: 1.1115x; 1.0809x over previous
#include <cuda_runtime.h>
#include <cuda_bf16.h>
#include <cstdint>

#define NB    8
#define NPTS  8192
#define E     128
#define HG    64
#define WG    64
#define SG    (HG*WG)          // 4096
#define NCELL (NB*SG)          // 32768
#define NPT   (NB*NPTS)        // 65536
#define NROWS (NPT+NCELL)      // 98304
#define MAXP  20
#define NH    8

#define SK 136                 // padded k-stride (bf16 elements)

// ---------------- scratch ----------------
__device__ int   g_count[NCELL];
__device__ int   g_slots[NCELL*MAXP];
__device__ float g_q[E];
__device__ float g_score[(size_t)NROWS*NH];    // point scores then grid scores
__device__ float g_V[(size_t)NROWS*E];         // z@Wv then z_grid@Wv
// attention output, pre-split bf16 hi/lo in GEMM A layout ([cell][k], SK stride)
__device__ __align__(16) __nv_bfloat16 g_AttH[(size_t)NCELL*SK];
__device__ __align__(16) __nv_bfloat16 g_AttL[(size_t)NCELL*SK];
// pre-split weights (bf16 hi/lo, transposed [n][k]):
// Wv blob = [Whi 128xSK][Wlo 128xSK][ATh 8xSK][ATl 8xSK]
__device__ __align__(16) __nv_bfloat16 g_WvSp[272*SK];
__device__ __align__(16) __nv_bfloat16 g_WoSp[256*SK];

// ---------------- mma / ldmatrix helpers ----------------
__device__ __forceinline__ void mma16816(float* c, const uint32_t* a, uint32_t b0, uint32_t b1) {
    asm volatile(
        "mma.sync.aligned.m16n8k16.row.col.f32.bf16.bf16.f32 "
        "{%0,%1,%2,%3}, {%4,%5,%6,%7}, {%8,%9}, {%0,%1,%2,%3};"
        : "+f"(c[0]), "+f"(c[1]), "+f"(c[2]), "+f"(c[3])
        : "r"(a[0]), "r"(a[1]), "r"(a[2]), "r"(a[3]), "r"(b0), "r"(b1));
}
__device__ __forceinline__ void ldsm_x4(uint32_t* r, uint32_t a) {
    asm volatile("ldmatrix.sync.aligned.m8n8.x4.shared.b16 {%0,%1,%2,%3}, [%4];"
        : "=r"(r[0]), "=r"(r[1]), "=r"(r[2]), "=r"(r[3]) : "r"(a));
}
__device__ __forceinline__ void ldsm_x2(uint32_t* r, uint32_t a) {
    asm volatile("ldmatrix.sync.aligned.m8n8.x2.shared.b16 {%0,%1}, [%2];"
        : "=r"(r[0]), "=r"(r[1]) : "r"(a));
}
__device__ __forceinline__ uint32_t pack_hi(float x, float y) {
    __nv_bfloat162 h = __halves2bfloat162(__float2bfloat16(x), __float2bfloat16(y));
    return *(uint32_t*)&h;
}
__device__ __forceinline__ uint32_t pack_lo(float x, float y) {
    __nv_bfloat16 hx = __float2bfloat16(x), hy = __float2bfloat16(y);
    __nv_bfloat162 l = __halves2bfloat162(__float2bfloat16(x - __bfloat162float(hx)),
                                          __float2bfloat16(y - __bfloat162float(hy)));
    return *(uint32_t*)&l;
}
__device__ __forceinline__ void cp_async16(uint32_t dst, const void* src) {
    asm volatile("cp.async.cg.shared.global [%0], [%1], 16;" :: "r"(dst), "l"(src));
}

// shared mainloop: A[64][128] hi/lo in smem, B[128][128] hi/lo in smem, 3-pass bf16
#define SM_AHI 0
#define SM_ALO (64*SK)
#define SM_BHI (128*SK)
#define SM_BLO (256*SK)
#define SM_SBH (384*SK)
#define SM_SBL (392*SK)
#define GEMM1_SMEM (400*SK*2)    // 108800 B  (with score cols)
#define GEMM2_SMEM (384*SK*2)    // 104448 B  (no score)

template<bool DO_SCORE>
__device__ __forceinline__ void gemm_mainloop(uint32_t sb, int wid, int lane,
                                              int gRow0, float* __restrict__ C,
                                              float* __restrict__ Sout) {
    const int mw = wid >> 2;            // 0..1 : rows mw*32
    const int nw = wid & 3;             // 0..3 : cols nw*32
    const int g  = lane >> 2;
    const int tg = lane & 3;

    uint32_t aAh[2], aAl[2];
    #pragma unroll
    for (int mt = 0; mt < 2; mt++) {
        int row = mw*32 + mt*16 + (lane & 15);
        int col = (lane >> 4) << 3;
        aAh[mt] = sb + (SM_AHI + row*SK + col) * 2;
        aAl[mt] = sb + (SM_ALO + row*SK + col) * 2;
    }
    uint32_t aBh[2], aBl[2];
    #pragma unroll
    for (int c = 0; c < 2; c++) {
        int row = nw*32 + c*16 + (lane & 7) + ((lane >> 4) << 3);
        int col = ((lane >> 3) & 1) << 3;
        aBh[c] = sb + (SM_BHI + row*SK + col) * 2;
        aBl[c] = sb + (SM_BLO + row*SK + col) * 2;
    }
    uint32_t aSh = 0, aSl = 0;
    if (DO_SCORE) {
        int row = lane & 7;
        int col = ((lane >> 3) & 1) << 3;
        aSh = sb + (SM_SBH + row*SK + col) * 2;
        aSl = sb + (SM_SBL + row*SK + col) * 2;
    }

    float acc[2][4][4];
    #pragma unroll
    for (int a = 0; a < 2; a++)
        #pragma unroll
        for (int b = 0; b < 4; b++)
            #pragma unroll
            for (int c = 0; c < 4; c++) acc[a][b][c] = 0.f;
    float sacc[2][4] = {{0.f,0.f,0.f,0.f},{0.f,0.f,0.f,0.f}};

    #pragma unroll
    for (int ks = 0; ks < 8; ks++) {
        const uint32_t ko = ks * 32;
        uint32_t ah[2][4], al[2][4];
        ldsm_x4(ah[0], aAh[0] + ko);
        ldsm_x4(ah[1], aAh[1] + ko);
        ldsm_x4(al[0], aAl[0] + ko);
        ldsm_x4(al[1], aAl[1] + ko);

        if (DO_SCORE && nw == 0) {
            uint32_t sh[2], sl[2];
            ldsm_x2(sh, aSh + ko);
            ldsm_x2(sl, aSl + ko);
            #pragma unroll
            for (int mt = 0; mt < 2; mt++) {
                mma16816(sacc[mt], ah[mt], sh[0], sh[1]);
                mma16816(sacc[mt], al[mt], sh[0], sh[1]);
                mma16816(sacc[mt], ah[mt], sl[0], sl[1]);
            }
        }
        #pragma unroll
        for (int c = 0; c < 2; c++) {
            uint32_t bh[4], bl[4];
            ldsm_x4(bh, aBh[c] + ko);
            ldsm_x4(bl, aBl[c] + ko);
            #pragma unroll
            for (int mt = 0; mt < 2; mt++) {
                mma16816(acc[mt][2*c+0], ah[mt], bh[0], bh[1]);
                mma16816(acc[mt][2*c+1], ah[mt], bh[2], bh[3]);
                mma16816(acc[mt][2*c+0], al[mt], bh[0], bh[1]);
                mma16816(acc[mt][2*c+1], al[mt], bh[2], bh[3]);
                mma16816(acc[mt][2*c+0], ah[mt], bl[0], bl[1]);
                mma16816(acc[mt][2*c+1], ah[mt], bl[2], bl[3]);
            }
        }
    }

    #pragma unroll
    for (int mt = 0; mt < 2; mt++) {
        int row = gRow0 + mw*32 + mt*16 + g;
        #pragma unroll
        for (int nt = 0; nt < 4; nt++) {
            int col = nw*32 + nt*8 + tg*2;
            *(float2*)(C + (size_t)row * E + col) =
                make_float2(acc[mt][nt][0], acc[mt][nt][1]);
            *(float2*)(C + (size_t)(row + 8) * E + col) =
                make_float2(acc[mt][nt][2], acc[mt][nt][3]);
        }
    }
    if (DO_SCORE && nw == 0) {
        #pragma unroll
        for (int mt = 0; mt < 2; mt++) {
            int row = gRow0 + mw*32 + mt*16 + g;
            *(float2*)(Sout + (size_t)row * NH + tg*2) =
                make_float2(sacc[mt][0], sacc[mt][1]);
            *(float2*)(Sout + (size_t)(row + 8) * NH + tg*2) =
                make_float2(sacc[mt][2], sacc[mt][3]);
        }
    }
}

// ---------------- GEMM 1: V = [z; z_grid] @ Wv  (+ scores) ----------------
__global__ void __launch_bounds__(256, 2) gemm_v(const float* __restrict__ Z1,
                                                 const float* __restrict__ Z2, int nb1,
                                                 float* __restrict__ C,
                                                 float* __restrict__ Sout) {
    extern __shared__ __nv_bfloat16 sm[];
    const int t    = threadIdx.x;
    const int wid  = t >> 5;
    const int lane = t & 31;
    const int gRow0 = blockIdx.x * 64;
    const float* src;
    int m0;
    if ((int)blockIdx.x < nb1) { src = Z1; m0 = gRow0; }
    else                       { src = Z2; m0 = (blockIdx.x - nb1) * 64; }

    const uint32_t sb = (uint32_t)__cvta_generic_to_shared(sm);

    // B (+score) staging: linear cp.async of pre-split blob
    {
        const char* gsrc = (const char*)g_WvSp;
        uint32_t bdst = sb + SM_BHI*2;
        const int wbytes = 272*SK*2;
        for (int off = t*16; off < wbytes; off += 256*16)
            cp_async16(bdst + off, gsrc + off);
        asm volatile("cp.async.commit_group;");
    }
    // A staging: each thread one quarter-row (32 floats), split hi/lo
    {
        int row = t >> 2;
        int kq  = (t & 3) << 5;
        const float4* zr = (const float4*)(src + (size_t)(m0 + row) * E + kq);
        __nv_bfloat16* ah = sm + SM_AHI + row*SK + kq;
        __nv_bfloat16* al = sm + SM_ALO + row*SK + kq;
        #pragma unroll
        for (int i = 0; i < 8; i++) {
            float4 v = zr[i];
            ((uint32_t*)(ah + i*4))[0] = pack_hi(v.x, v.y);
            ((uint32_t*)(ah + i*4))[1] = pack_hi(v.z, v.w);
            ((uint32_t*)(al + i*4))[0] = pack_lo(v.x, v.y);
            ((uint32_t*)(al + i*4))[1] = pack_lo(v.z, v.w);
        }
    }
    asm volatile("cp.async.wait_group 0;" ::: "memory");
    __syncthreads();

    gemm_mainloop<true>(sb, wid, lane, gRow0, C, Sout);
}

// ---------------- attn: single-pass softmax-weighted V mix, writes split bf16 blob ----------------
__global__ void attn_kernel() {
    const float* V   = g_V;
    const float* gV  = g_V + (size_t)NPT*E;
    const float* Ssc = g_score;
    const float* gS  = g_score + (size_t)NPT*NH;

    __shared__ int toks[8][MAXP];
    int warp = threadIdx.x >> 5, lane = threadIdx.x & 31;
    int c = blockIdx.x*8 + warp;
    int kk = min(g_count[c], MAXP);
    if (lane < kk) toks[warp][lane] = g_slots[c*MAXP + lane];
    __syncwarp();

    int h = lane >> 2;
    float e = __expf(gS[(size_t)c*NH + h]);
    float sum = e;
    float4 gv = *(const float4*)(gV + (size_t)c*E + lane*4);
    float4 acc = make_float4(e*gv.x, e*gv.y, e*gv.z, e*gv.w);
    for (int tkn = 0; tkn < kk; tkn++) {
        int p = toks[warp][tkn];
        float w = __expf(Ssc[(size_t)p*NH + h]);
        sum += w;
        float4 v = *(const float4*)(V + (size_t)p*E + lane*4);
        acc.x += w*v.x; acc.y += w*v.y; acc.z += w*v.z; acc.w += w*v.w;
    }
    float inv = 1.0f / sum;
    acc.x *= inv; acc.y *= inv; acc.z *= inv; acc.w *= inv;

    uint2 hi = make_uint2(pack_hi(acc.x, acc.y), pack_hi(acc.z, acc.w));
    uint2 lo = make_uint2(pack_lo(acc.x, acc.y), pack_lo(acc.z, acc.w));
    *(uint2*)(g_AttH + (size_t)c*SK + lane*4) = hi;
    *(uint2*)(g_AttL + (size_t)c*SK + lane*4) = lo;
}

// ---------------- GEMM 2: out = att @ Wo, A pre-split -> pure cp.async staging ----------------
__global__ void __launch_bounds__(256, 2) gemm_o(float* __restrict__ C) {
    extern __shared__ __nv_bfloat16 sm[];
    const int t    = threadIdx.x;
    const int wid  = t >> 5;
    const int lane = t & 31;
    const int c0   = blockIdx.x * 64;

    const uint32_t sb = (uint32_t)__cvta_generic_to_shared(sm);

    // B staging
    {
        const char* gsrc = (const char*)g_WoSp;
        uint32_t bdst = sb + SM_BHI*2;
        const int wbytes = 256*SK*2;
        for (int off = t*16; off < wbytes; off += 256*16)
            cp_async16(bdst + off, gsrc + off);
    }
    // A staging: linear cp.async of pre-split attn blob (64 rows x SK, hi + lo)
    {
        const char* hsrc = (const char*)(g_AttH + (size_t)c0*SK);
        const char* lsrc = (const char*)(g_AttL + (size_t)c0*SK);
        const int abytes = 64*SK*2;       // 17408
        for (int off = t*16; off < abytes; off += 256*16) {
            cp_async16(sb + SM_AHI*2 + off, hsrc + off);
            cp_async16(sb + SM_ALO*2 + off, lsrc + off);
        }
        asm volatile("cp.async.commit_group;");
    }
    asm volatile("cp.async.wait_group 0;" ::: "memory");
    __syncthreads();

    gemm_mainloop<false>(sb, wid, lane, c0, C, nullptr);
}

// ---------------- fused setup kernels ----------------
// setup1: blocks 0..127 -> split+transpose Wv & Wo; block 128 -> q = latent@Wq;
//         blocks 129..256 -> zero g_count
__global__ void setup1(const float* __restrict__ Wv, const float* __restrict__ Wo,
                       const float* __restrict__ latent, const float* __restrict__ Wq) {
    __shared__ float lat[E];
    __shared__ float part[2][E];
    int b = blockIdx.x;
    int t = threadIdx.x;
    if (b < 128) {
        int n = b;
        if (t < 128) {
            int k = t;
            float v = Wv[(size_t)k*E + n];
            __nv_bfloat16 h = __float2bfloat16(v);
            g_WvSp[n*SK + k] = h;
            g_WvSp[128*SK + n*SK + k] = __float2bfloat16(v - __bfloat162float(h));
        } else {
            int k = t - 128;
            float v = Wo[(size_t)k*E + n];
            __nv_bfloat16 h = __float2bfloat16(v);
            g_WoSp[n*SK + k] = h;
            g_WoSp[128*SK + n*SK + k] = __float2bfloat16(v - __bfloat162float(h));
        }
    } else if (b == 128) {
        int tt = t & 127;
        int dd = t >> 7;       // 0..1
        if (t < E) lat[t] = latent[t];
        __syncthreads();
        float a = 0.f;
        #pragma unroll
        for (int i = 0; i < 64; i++) {
            int d = dd*64 + i;
            a += lat[d] * Wq[(size_t)d*E + tt];
        }
        part[dd][tt] = a;
        __syncthreads();
        if (t < E) g_q[t] = part[0][t] + part[1][t];
    } else {
        g_count[(b - 129)*256 + t] = 0;
    }
}

// setup2: blocks 0..3 -> AT[h][k] hi/lo into Wv blob tail; blocks 4..259 -> scatter
__global__ void setup2(const float* __restrict__ Wk, const float* __restrict__ x) {
    __shared__ float qs[E];
    int b = blockIdx.x;
    int t = threadIdx.x;
    if (b < 4) {
        if (t < E) qs[t] = g_q[t];
        __syncthreads();
        int id = b*256 + t;          // 0..1023
        int k = id >> 3, h = id & 7;
        float s = 0.f;
        #pragma unroll
        for (int i = 0; i < 16; i++) s += Wk[(size_t)k*E + h*16 + i] * qs[h*16 + i];
        s *= 0.25f;
        __nv_bfloat16 hi = __float2bfloat16(s);
        g_WvSp[256*SK + h*SK + k] = hi;
        g_WvSp[264*SK + h*SK + k] = __float2bfloat16(s - __bfloat162float(hi));
    } else {
        int p = (b - 4)*256 + t;
        int bb = p >> 13;
        float x0 = x[2*p], x1 = x[2*p+1];
        int i0 = (int)rintf(x0 * 63.0f); i0 = min(max(i0, 0), 63);
        int i1 = (int)rintf(x1 * 63.0f); i1 = min(max(i1, 0), 63);
        int cell = bb*SG + i0*WG + i1;
        int slot = atomicAdd(&g_count[cell], 1);
        if (slot < MAXP) g_slots[cell*MAXP + slot] = p;
    }
}

// ---------------- launch ----------------
extern "C" void kernel_launch(void* const* d_in, const int* in_sizes, int n_in,
                              void* d_out, int out_size) {
    const float* x      = (const float*)d_in[0];
    const float* z      = (const float*)d_in[1];
    const float* x_grid = (const float*)d_in[2];
    const float* z_grid = (const float*)d_in[3];
    const float* latent = (const float*)d_in[4];
    const float* Wq     = (const float*)d_in[5];
    const float* Wk     = (const float*)d_in[6];
    const float* Wv     = (const float*)d_in[7];
    const float* Wo     = (const float*)d_in[8];

    float* out = (float*)d_out;
    float* zg_out = out;
    const int XG_ELEMS = NB*SG*2;
    if (out_size == NCELL*E + XG_ELEMS) {
        cudaMemcpyAsync(out, x_grid, (size_t)XG_ELEMS*sizeof(float),
                        cudaMemcpyDeviceToDevice);
        zg_out = out + XG_ELEMS;
    }

    void *pV, *pS;
    cudaGetSymbolAddress(&pV, g_V);
    cudaGetSymbolAddress(&pS, g_score);

    cudaFuncSetAttribute(gemm_v, cudaFuncAttributeMaxDynamicSharedMemorySize, GEMM1_SMEM);
    cudaFuncSetAttribute(gemm_o, cudaFuncAttributeMaxDynamicSharedMemorySize, GEMM2_SMEM);

    setup1<<<257, 256>>>(Wv, Wo, latent, Wq);
    setup2<<<260, 256>>>(Wk, x);

    gemm_v<<<NROWS/64, 256, GEMM1_SMEM>>>(z, z_grid, NPT/64, (float*)pV, (float*)pS);
    attn_kernel<<<NCELL/8, 256>>>();
    gemm_o<<<NCELL/64, 256, GEMM2_SMEM>>>(zg_out);
}

// round 16
// speedup vs baseline: 1.1441x; 1.0293x over previous
#include <cuda_runtime.h>
#include <cuda_bf16.h>
#include <cstdint>

#define NB    8
#define NPTS  8192
#define E     128
#define HG    64
#define WG    64
#define SG    (HG*WG)          // 4096
#define NCELL (NB*SG)          // 32768
#define NPT   (NB*NPTS)        // 65536
#define NROWS (NPT+NCELL)      // 98304
#define MAXP  20
#define NH    8

#define SK 136                 // padded k-stride (bf16 elements)

// ---------------- scratch ----------------
__device__ int   g_count[NCELL];               // zero at load; attn re-zeroes after use
__device__ int   g_slots[NCELL*MAXP];
__device__ float g_score[(size_t)NROWS*NH];    // point scores then grid scores
__device__ float g_V[(size_t)NROWS*E];         // z@Wv then z_grid@Wv
// attention output, pre-split bf16 hi/lo in GEMM A layout ([cell][k], SK stride)
__device__ __align__(16) __nv_bfloat16 g_AttH[(size_t)NCELL*SK];
__device__ __align__(16) __nv_bfloat16 g_AttL[(size_t)NCELL*SK];
// pre-split weights (bf16 hi/lo, transposed [n][k]):
// Wv blob = [Whi 128xSK][Wlo 128xSK][ATh 8xSK][ATl 8xSK]
__device__ __align__(16) __nv_bfloat16 g_WvSp[272*SK];
__device__ __align__(16) __nv_bfloat16 g_WoSp[256*SK];

// ---------------- mma / ldmatrix helpers ----------------
__device__ __forceinline__ void mma16816(float* c, const uint32_t* a, uint32_t b0, uint32_t b1) {
    asm volatile(
        "mma.sync.aligned.m16n8k16.row.col.f32.bf16.bf16.f32 "
        "{%0,%1,%2,%3}, {%4,%5,%6,%7}, {%8,%9}, {%0,%1,%2,%3};"
        : "+f"(c[0]), "+f"(c[1]), "+f"(c[2]), "+f"(c[3])
        : "r"(a[0]), "r"(a[1]), "r"(a[2]), "r"(a[3]), "r"(b0), "r"(b1));
}
__device__ __forceinline__ void ldsm_x4(uint32_t* r, uint32_t a) {
    asm volatile("ldmatrix.sync.aligned.m8n8.x4.shared.b16 {%0,%1,%2,%3}, [%4];"
        : "=r"(r[0]), "=r"(r[1]), "=r"(r[2]), "=r"(r[3]) : "r"(a));
}
__device__ __forceinline__ void ldsm_x2(uint32_t* r, uint32_t a) {
    asm volatile("ldmatrix.sync.aligned.m8n8.x2.shared.b16 {%0,%1}, [%2];"
        : "=r"(r[0]), "=r"(r[1]) : "r"(a));
}
__device__ __forceinline__ uint32_t pack_hi(float x, float y) {
    __nv_bfloat162 h = __halves2bfloat162(__float2bfloat16(x), __float2bfloat16(y));
    return *(uint32_t*)&h;
}
__device__ __forceinline__ uint32_t pack_lo(float x, float y) {
    __nv_bfloat16 hx = __float2bfloat16(x), hy = __float2bfloat16(y);
    __nv_bfloat162 l = __halves2bfloat162(__float2bfloat16(x - __bfloat162float(hx)),
                                          __float2bfloat16(y - __bfloat162float(hy)));
    return *(uint32_t*)&l;
}
__device__ __forceinline__ void cp_async16(uint32_t dst, const void* src) {
    asm volatile("cp.async.cg.shared.global [%0], [%1], 16;" :: "r"(dst), "l"(src));
}

// shared mainloop: A[64][128] hi/lo in smem, B[128][128] hi/lo in smem, 3-pass bf16
#define SM_AHI 0
#define SM_ALO (64*SK)
#define SM_BHI (128*SK)
#define SM_BLO (256*SK)
#define SM_SBH (384*SK)
#define SM_SBL (392*SK)
#define GEMM1_SMEM (400*SK*2)    // 108800 B  (with score cols)
#define GEMM2_SMEM (384*SK*2)    // 104448 B  (no score)

template<bool DO_SCORE>
__device__ __forceinline__ void gemm_mainloop(uint32_t sb, int wid, int lane,
                                              int gRow0, float* __restrict__ C,
                                              float* __restrict__ Sout) {
    const int mw = wid >> 2;            // 0..1 : rows mw*32
    const int nw = wid & 3;             // 0..3 : cols nw*32
    const int g  = lane >> 2;
    const int tg = lane & 3;

    uint32_t aAh[2], aAl[2];
    #pragma unroll
    for (int mt = 0; mt < 2; mt++) {
        int row = mw*32 + mt*16 + (lane & 15);
        int col = (lane >> 4) << 3;
        aAh[mt] = sb + (SM_AHI + row*SK + col) * 2;
        aAl[mt] = sb + (SM_ALO + row*SK + col) * 2;
    }
    uint32_t aBh[2], aBl[2];
    #pragma unroll
    for (int c = 0; c < 2; c++) {
        int row = nw*32 + c*16 + (lane & 7) + ((lane >> 4) << 3);
        int col = ((lane >> 3) & 1) << 3;
        aBh[c] = sb + (SM_BHI + row*SK + col) * 2;
        aBl[c] = sb + (SM_BLO + row*SK + col) * 2;
    }
    uint32_t aSh = 0, aSl = 0;
    if (DO_SCORE) {
        int row = lane & 7;
        int col = ((lane >> 3) & 1) << 3;
        aSh = sb + (SM_SBH + row*SK + col) * 2;
        aSl = sb + (SM_SBL + row*SK + col) * 2;
    }

    float acc[2][4][4];
    #pragma unroll
    for (int a = 0; a < 2; a++)
        #pragma unroll
        for (int b = 0; b < 4; b++)
            #pragma unroll
            for (int c = 0; c < 4; c++) acc[a][b][c] = 0.f;
    float sacc[2][4] = {{0.f,0.f,0.f,0.f},{0.f,0.f,0.f,0.f}};

    #pragma unroll
    for (int ks = 0; ks < 8; ks++) {
        const uint32_t ko = ks * 32;
        uint32_t ah[2][4], al[2][4];
        ldsm_x4(ah[0], aAh[0] + ko);
        ldsm_x4(ah[1], aAh[1] + ko);
        ldsm_x4(al[0], aAl[0] + ko);
        ldsm_x4(al[1], aAl[1] + ko);

        if (DO_SCORE && nw == 0) {
            uint32_t sh[2], sl[2];
            ldsm_x2(sh, aSh + ko);
            ldsm_x2(sl, aSl + ko);
            #pragma unroll
            for (int mt = 0; mt < 2; mt++) {
                mma16816(sacc[mt], ah[mt], sh[0], sh[1]);
                mma16816(sacc[mt], al[mt], sh[0], sh[1]);
                mma16816(sacc[mt], ah[mt], sl[0], sl[1]);
            }
        }
        #pragma unroll
        for (int c = 0; c < 2; c++) {
            uint32_t bh[4], bl[4];
            ldsm_x4(bh, aBh[c] + ko);
            ldsm_x4(bl, aBl[c] + ko);
            #pragma unroll
            for (int mt = 0; mt < 2; mt++) {
                mma16816(acc[mt][2*c+0], ah[mt], bh[0], bh[1]);
                mma16816(acc[mt][2*c+1], ah[mt], bh[2], bh[3]);
                mma16816(acc[mt][2*c+0], al[mt], bh[0], bh[1]);
                mma16816(acc[mt][2*c+1], al[mt], bh[2], bh[3]);
                mma16816(acc[mt][2*c+0], ah[mt], bl[0], bl[1]);
                mma16816(acc[mt][2*c+1], ah[mt], bl[2], bl[3]);
            }
        }
    }

    #pragma unroll
    for (int mt = 0; mt < 2; mt++) {
        int row = gRow0 + mw*32 + mt*16 + g;
        #pragma unroll
        for (int nt = 0; nt < 4; nt++) {
            int col = nw*32 + nt*8 + tg*2;
            *(float2*)(C + (size_t)row * E + col) =
                make_float2(acc[mt][nt][0], acc[mt][nt][1]);
            *(float2*)(C + (size_t)(row + 8) * E + col) =
                make_float2(acc[mt][nt][2], acc[mt][nt][3]);
        }
    }
    if (DO_SCORE && nw == 0) {
        #pragma unroll
        for (int mt = 0; mt < 2; mt++) {
            int row = gRow0 + mw*32 + mt*16 + g;
            *(float2*)(Sout + (size_t)row * NH + tg*2) =
                make_float2(sacc[mt][0], sacc[mt][1]);
            *(float2*)(Sout + (size_t)(row + 8) * NH + tg*2) =
                make_float2(sacc[mt][2], sacc[mt][3]);
        }
    }
}

// ---------------- GEMM 1: V = [z; z_grid] @ Wv  (+ scores) ----------------
__global__ void __launch_bounds__(256, 2) gemm_v(const float* __restrict__ Z1,
                                                 const float* __restrict__ Z2, int nb1,
                                                 float* __restrict__ C,
                                                 float* __restrict__ Sout) {
    extern __shared__ __nv_bfloat16 sm[];
    const int t    = threadIdx.x;
    const int wid  = t >> 5;
    const int lane = t & 31;
    const int gRow0 = blockIdx.x * 64;
    const float* src;
    int m0;
    if ((int)blockIdx.x < nb1) { src = Z1; m0 = gRow0; }
    else                       { src = Z2; m0 = (blockIdx.x - nb1) * 64; }

    const uint32_t sb = (uint32_t)__cvta_generic_to_shared(sm);

    // B (+score) staging: linear cp.async of pre-split blob
    {
        const char* gsrc = (const char*)g_WvSp;
        uint32_t bdst = sb + SM_BHI*2;
        const int wbytes = 272*SK*2;
        for (int off = t*16; off < wbytes; off += 256*16)
            cp_async16(bdst + off, gsrc + off);
        asm volatile("cp.async.commit_group;");
    }
    // A staging: each thread one quarter-row (32 floats), split hi/lo
    {
        int row = t >> 2;
        int kq  = (t & 3) << 5;
        const float4* zr = (const float4*)(src + (size_t)(m0 + row) * E + kq);
        __nv_bfloat16* ah = sm + SM_AHI + row*SK + kq;
        __nv_bfloat16* al = sm + SM_ALO + row*SK + kq;
        #pragma unroll
        for (int i = 0; i < 8; i++) {
            float4 v = zr[i];
            ((uint32_t*)(ah + i*4))[0] = pack_hi(v.x, v.y);
            ((uint32_t*)(ah + i*4))[1] = pack_hi(v.z, v.w);
            ((uint32_t*)(al + i*4))[0] = pack_lo(v.x, v.y);
            ((uint32_t*)(al + i*4))[1] = pack_lo(v.z, v.w);
        }
    }
    asm volatile("cp.async.wait_group 0;" ::: "memory");
    __syncthreads();

    gemm_mainloop<true>(sb, wid, lane, gRow0, C, Sout);
}

// ---------------- attn: half-warp per cell, single-pass softmax, resets g_count ----------------
__global__ void attn_kernel() {
    const float* V   = g_V;
    const float* gV  = g_V + (size_t)NPT*E;
    const float* Ssc = g_score;
    const float* gS  = g_score + (size_t)NPT*NH;

    __shared__ int toks[16][MAXP];
    int hw     = threadIdx.x >> 4;       // half-warp id 0..15
    int lane16 = threadIdx.x & 15;
    int c = blockIdx.x*16 + hw;
    int kk = min(g_count[c], MAXP);
    if (lane16 < kk)       toks[hw][lane16]      = g_slots[c*MAXP + lane16];
    if (lane16 + 16 < kk)  toks[hw][lane16 + 16] = g_slots[c*MAXP + lane16 + 16];
    if (lane16 == 0) g_count[c] = 0;     // reset for next graph replay
    __syncwarp();

    int h = lane16 >> 1;                 // head for cols lane16*8 .. +7
    float e = __expf(gS[(size_t)c*NH + h]);
    float sum = e;
    const float* gvr = gV + (size_t)c*E + lane16*8;
    float4 gv0 = *(const float4*)(gvr);
    float4 gv1 = *(const float4*)(gvr + 4);
    float4 a0 = make_float4(e*gv0.x, e*gv0.y, e*gv0.z, e*gv0.w);
    float4 a1 = make_float4(e*gv1.x, e*gv1.y, e*gv1.z, e*gv1.w);
    for (int tkn = 0; tkn < kk; tkn++) {
        int p = toks[hw][tkn];
        float w = __expf(Ssc[(size_t)p*NH + h]);
        sum += w;
        const float* vr = V + (size_t)p*E + lane16*8;
        float4 v0 = *(const float4*)(vr);
        float4 v1 = *(const float4*)(vr + 4);
        a0.x += w*v0.x; a0.y += w*v0.y; a0.z += w*v0.z; a0.w += w*v0.w;
        a1.x += w*v1.x; a1.y += w*v1.y; a1.z += w*v1.z; a1.w += w*v1.w;
    }
    float inv = 1.0f / sum;
    a0.x *= inv; a0.y *= inv; a0.z *= inv; a0.w *= inv;
    a1.x *= inv; a1.y *= inv; a1.z *= inv; a1.w *= inv;

    uint4 hi = make_uint4(pack_hi(a0.x, a0.y), pack_hi(a0.z, a0.w),
                          pack_hi(a1.x, a1.y), pack_hi(a1.z, a1.w));
    uint4 lo = make_uint4(pack_lo(a0.x, a0.y), pack_lo(a0.z, a0.w),
                          pack_lo(a1.x, a1.y), pack_lo(a1.z, a1.w));
    *(uint4*)(g_AttH + (size_t)c*SK + lane16*8) = hi;
    *(uint4*)(g_AttL + (size_t)c*SK + lane16*8) = lo;
}

// ---------------- GEMM 2: out = att @ Wo, A pre-split -> pure cp.async staging ----------------
__global__ void __launch_bounds__(256, 2) gemm_o(float* __restrict__ C) {
    extern __shared__ __nv_bfloat16 sm[];
    const int t    = threadIdx.x;
    const int wid  = t >> 5;
    const int lane = t & 31;
    const int c0   = blockIdx.x * 64;

    const uint32_t sb = (uint32_t)__cvta_generic_to_shared(sm);

    // B staging
    {
        const char* gsrc = (const char*)g_WoSp;
        uint32_t bdst = sb + SM_BHI*2;
        const int wbytes = 256*SK*2;
        for (int off = t*16; off < wbytes; off += 256*16)
            cp_async16(bdst + off, gsrc + off);
    }
    // A staging: linear cp.async of pre-split attn blob (64 rows x SK, hi + lo)
    {
        const char* hsrc = (const char*)(g_AttH + (size_t)c0*SK);
        const char* lsrc = (const char*)(g_AttL + (size_t)c0*SK);
        const int abytes = 64*SK*2;       // 17408
        for (int off = t*16; off < abytes; off += 256*16) {
            cp_async16(sb + SM_AHI*2 + off, hsrc + off);
            cp_async16(sb + SM_ALO*2 + off, lsrc + off);
        }
        asm volatile("cp.async.commit_group;");
    }
    asm volatile("cp.async.wait_group 0;" ::: "memory");
    __syncthreads();

    gemm_mainloop<false>(sb, wid, lane, c0, C, nullptr);
}

// ---------------- single fused setup kernel ----------------
// blocks 0..127   : split+transpose Wv & Wo (block = output row n)
// block 128       : q = latent@Wq then AT[h][k] hi/lo into Wv blob tail (same block via smem)
// blocks 129..384 : scatter points into cells (g_count starts 0: module init / attn reset)
__global__ void setup(const float* __restrict__ Wv, const float* __restrict__ Wo,
                      const float* __restrict__ latent, const float* __restrict__ Wq,
                      const float* __restrict__ Wk, const float* __restrict__ x) {
    __shared__ float lat[E];
    __shared__ float part[2][E];
    __shared__ float qs[E];
    int b = blockIdx.x;
    int t = threadIdx.x;
    if (b < 128) {
        int n = b;
        if (t < 128) {
            int k = t;
            float v = Wv[(size_t)k*E + n];
            __nv_bfloat16 h = __float2bfloat16(v);
            g_WvSp[n*SK + k] = h;
            g_WvSp[128*SK + n*SK + k] = __float2bfloat16(v - __bfloat162float(h));
        } else {
            int k = t - 128;
            float v = Wo[(size_t)k*E + n];
            __nv_bfloat16 h = __float2bfloat16(v);
            g_WoSp[n*SK + k] = h;
            g_WoSp[128*SK + n*SK + k] = __float2bfloat16(v - __bfloat162float(h));
        }
    } else if (b == 128) {
        int tt = t & 127;
        int dd = t >> 7;       // 0..1
        if (t < E) lat[t] = latent[t];
        __syncthreads();
        float a = 0.f;
        #pragma unroll
        for (int i = 0; i < 64; i++) {
            int d = dd*64 + i;
            a += lat[d] * Wq[(size_t)d*E + tt];
        }
        part[dd][tt] = a;
        __syncthreads();
        if (t < E) qs[t] = part[0][t] + part[1][t];
        __syncthreads();
        #pragma unroll
        for (int r = 0; r < 4; r++) {
            int id = r*256 + t;          // 0..1023
            int k = id >> 3, h = id & 7;
            float s = 0.f;
            #pragma unroll
            for (int i = 0; i < 16; i++) s += Wk[(size_t)k*E + h*16 + i] * qs[h*16 + i];
            s *= 0.25f;
            __nv_bfloat16 hi = __float2bfloat16(s);
            g_WvSp[256*SK + h*SK + k] = hi;
            g_WvSp[264*SK + h*SK + k] = __float2bfloat16(s - __bfloat162float(hi));
        }
    } else {
        int p = (b - 129)*256 + t;
        int bb = p >> 13;
        float x0 = x[2*p], x1 = x[2*p+1];
        int i0 = (int)rintf(x0 * 63.0f); i0 = min(max(i0, 0), 63);
        int i1 = (int)rintf(x1 * 63.0f); i1 = min(max(i1, 0), 63);
        int cell = bb*SG + i0*WG + i1;
        int slot = atomicAdd(&g_count[cell], 1);
        if (slot < MAXP) g_slots[cell*MAXP + slot] = p;
    }
}

// ---------------- launch ----------------
extern "C" void kernel_launch(void* const* d_in, const int* in_sizes, int n_in,
                              void* d_out, int out_size) {
    const float* x      = (const float*)d_in[0];
    const float* z      = (const float*)d_in[1];
    const float* x_grid = (const float*)d_in[2];
    const float* z_grid = (const float*)d_in[3];
    const float* latent = (const float*)d_in[4];
    const float* Wq     = (const float*)d_in[5];
    const float* Wk     = (const float*)d_in[6];
    const float* Wv     = (const float*)d_in[7];
    const float* Wo     = (const float*)d_in[8];

    float* out = (float*)d_out;
    float* zg_out = out;
    const int XG_ELEMS = NB*SG*2;
    if (out_size == NCELL*E + XG_ELEMS) {
        cudaMemcpyAsync(out, x_grid, (size_t)XG_ELEMS*sizeof(float),
                        cudaMemcpyDeviceToDevice);
        zg_out = out + XG_ELEMS;
    }

    void *pV, *pS;
    cudaGetSymbolAddress(&pV, g_V);
    cudaGetSymbolAddress(&pS, g_score);

    cudaFuncSetAttribute(gemm_v, cudaFuncAttributeMaxDynamicSharedMemorySize, GEMM1_SMEM);
    cudaFuncSetAttribute(gemm_o, cudaFuncAttributeMaxDynamicSharedMemorySize, GEMM2_SMEM);

    setup<<<385, 256>>>(Wv, Wo, latent, Wq, Wk, x);

    gemm_v<<<NROWS/64, 256, GEMM1_SMEM>>>(z, z_grid, NPT/64, (float*)pV, (float*)pS);
    attn_kernel<<<NCELL/16, 256>>>();
    gemm_o<<<NCELL/64, 256, GEMM2_SMEM>>>(zg_out);
}